// round 3
// baseline (speedup 1.0000x reference)
#include <cuda_runtime.h>
#include <math_constants.h>
#include <cfloat>

#define NN 8192
#define DD 128
#define TOPK 32

// Per-feature top-K, TRANSPOSED layout: g_topv[k*DD + d] (k-th largest of feature d).
__device__ __align__(16) float g_topv[TOPK * DD];
__device__ __align__(16) int   g_topi[TOPK * DD];

// ---------------------------------------------------------------------------
// Kernel 1: per-feature top-K selection. One CTA (1024 thr = 32 warps) per
// feature. Phase 1: each warp builds a sorted top-32 of its 256 rows with
// warp-only reductions (no block barriers). Phase 2: warp 0 merges the 32
// sorted lists with 32 argmax steps.
// ---------------------------------------------------------------------------
__global__ __launch_bounds__(1024) void topk_kernel(const float* __restrict__ x) {
    const int d   = blockIdx.x;
    const int tid = threadIdx.x;
    const int w   = tid >> 5;
    const int l   = tid & 31;

    float v[8];
    int   ri[8];
#pragma unroll
    for (int j = 0; j < 8; j++) {
        int r = w * 256 + j * 32 + l;
        ri[j] = r;
        v[j]  = x[(size_t)r * DD + d];
    }

    __shared__ float s_v[32 * 32];
    __shared__ int   s_i[32 * 32];

    // Phase 1: warp-local sorted top-32 (descending) via iterative argmax.
    for (int k = 0; k < TOPK; k++) {
        float bv = v[0]; int bi = ri[0];
#pragma unroll
        for (int j = 1; j < 8; j++)
            if (v[j] > bv) { bv = v[j]; bi = ri[j]; }
        // Butterfly argmax with deterministic tie-break on index so ALL lanes
        // converge to the same winner (prevents double-clear on value ties).
#pragma unroll
        for (int o = 16; o > 0; o >>= 1) {
            float ov = __shfl_xor_sync(0xffffffffu, bv, o);
            int   oi = __shfl_xor_sync(0xffffffffu, bi, o);
            if (ov > bv || (ov == bv && oi < bi)) { bv = ov; bi = oi; }
        }
        if (l == 0) { s_v[w * 32 + k] = bv; s_i[w * 32 + k] = bi; }
        // Owner lane clears the winning element (row indices are unique).
#pragma unroll
        for (int j = 0; j < 8; j++)
            if (ri[j] == bi) v[j] = -CUDART_INF_F;
    }
    __syncthreads();

    // Phase 2: warp 0 merges 32 sorted lists (lane l owns list l).
    if (w == 0) {
        int   p  = 0;
        float hv = s_v[l * 32];
        int   hi = s_i[l * 32];
        for (int k = 0; k < TOPK; k++) {
            float bv = hv; int bi = hi; int bl = l;
#pragma unroll
            for (int o = 16; o > 0; o >>= 1) {
                float ov = __shfl_xor_sync(0xffffffffu, bv, o);
                int   oi = __shfl_xor_sync(0xffffffffu, bi, o);
                int   ol = __shfl_xor_sync(0xffffffffu, bl, o);
                if (ov > bv || (ov == bv && ol < bl)) { bv = ov; bi = oi; bl = ol; }
            }
            if (l == 0) {
                g_topv[k * DD + d] = bv;   // transposed layout
                g_topi[k * DD + d] = bi;
            }
            if (bl == l) {                 // winner lane advances its list
                p++;
                hv = (p < 32) ? s_v[l * 32 + p] : -CUDART_INF_F;
                hi = (p < 32) ? s_i[l * 32 + p] : -1;
            }
        }
    }
}

// ---------------------------------------------------------------------------
// Kernel 2: probe. One warp per row; lane owns features d = f*32 + lane.
// All 4 features advance INTERLEAVED: up to 4 independent probe loads per
// trip, and probe k is only issued after probe k-1 missed -> minimal DRAM
// traffic with MLP=4. smem tables are [k][d] so LDS is bank-conflict-free
// even with per-lane k divergence (bank = d % 32 = lane).
// ---------------------------------------------------------------------------
__global__ __launch_bounds__(512) void probe_kernel(const float* __restrict__ x,
                                                    const int*   __restrict__ adj,
                                                    float*       __restrict__ out) {
    __shared__ __align__(16) float s_topv[TOPK * DD];
    __shared__ __align__(16) int   s_topi[TOPK * DD];
    {
        const float4* gv = (const float4*)g_topv;
        const int4*   gi = (const int4*)g_topi;
        float4* sv = (float4*)s_topv;
        int4*   si = (int4*)s_topi;
        for (int t = threadIdx.x; t < TOPK * DD / 4; t += blockDim.x) {
            sv[t] = gv[t];
            si[t] = gi[t];
        }
    }
    __syncthreads();

    const int warp = threadIdx.x >> 5;
    const int lane = threadIdx.x & 31;
    const int row  = blockIdx.x * 16 + warp;
    const int* __restrict__ arow = adj + (size_t)row * NN;

    // per-feature smem column offset: d = f*32 + lane
    int doff[4];
#pragma unroll
    for (int f = 0; f < 4; f++) doff[f] = f * 32 + lane;

    int      k[4]  = {0, 0, 0, 0};
    float    res[4];
    unsigned done = 0;
    unsigned fb   = 0;

#pragma unroll 1
    while (done != 0xFu) {
        int cc[4], a[4];
        // gather candidate columns (conflict-free LDS)
#pragma unroll
        for (int f = 0; f < 4; f++)
            if (!((done >> f) & 1))
                cc[f] = s_topi[k[f] * DD + doff[f]];
        // issue up to 4 independent probes
#pragma unroll
        for (int f = 0; f < 4; f++)
            if (!((done >> f) & 1))
                a[f] = __ldcs(arow + cc[f]);
        // resolve
#pragma unroll
        for (int f = 0; f < 4; f++) {
            if (!((done >> f) & 1)) {
                if (a[f] != 0) {
                    res[f] = s_topv[k[f] * DD + doff[f]];
                    done |= 1u << f;
                } else if (++k[f] == TOPK) {
                    fb   |= 1u << f;      // exact fallback needed (~never)
                    done |= 1u << f;
                }
            }
        }
    }

    if (fb) {  // exact fallback: full masked row scan (also no-neighbor -> 0)
#pragma unroll 1
        for (int f = 0; f < 4; f++) {
            if ((fb >> f) & 1) {
                const int d = doff[f];
                float m = -FLT_MAX; int any = 0;
                for (int j = 0; j < NN; j++) {
                    if (arow[j] != 0) { any = 1; m = fmaxf(m, x[(size_t)j * DD + d]); }
                }
                res[f] = any ? m : 0.0f;
            }
        }
    }

#pragma unroll
    for (int f = 0; f < 4; f++)
        out[(size_t)row * DD + doff[f]] = res[f];
}

extern "C" void kernel_launch(void* const* d_in, const int* in_sizes, int n_in,
                              void* d_out, int out_size) {
    const float* x   = (const float*)d_in[0];
    const int*   adj = (const int*)d_in[1];
    float*       out = (float*)d_out;

    topk_kernel<<<DD, 1024>>>(x);
    probe_kernel<<<NN / 16, 512>>>(x, adj, out);
}

// round 6
// speedup vs baseline: 1.0040x; 1.0040x over previous
#include <cuda_runtime.h>
#include <math_constants.h>
#include <cfloat>

#define NN 8192
#define DD 128
#define TOPK 32

// Per-feature top-K values and row indices, layout [d][k] (R1-proven).
__device__ __align__(16) float g_topv[DD * TOPK];
__device__ __align__(16) int   g_topi[DD * TOPK];

// ---------------------------------------------------------------------------
// Kernel 1: per-feature top-K selection (R1-proven version, verbatim).
// One CTA (1024 threads) per feature d. Each thread holds 8 column values in
// registers; 32 iterations of block argmax, clearing the winner each time.
// ---------------------------------------------------------------------------
__global__ __launch_bounds__(1024) void topk_kernel(const float* __restrict__ x) {
    const int d   = blockIdx.x;
    const int tid = threadIdx.x;

    float v[8];
#pragma unroll
    for (int j = 0; j < 8; j++)
        v[j] = x[(size_t)(j * 1024 + tid) * DD + d];

    __shared__ float s_wv[32];
    __shared__ int   s_wi[32];
    __shared__ int   s_bi;

    for (int k = 0; k < TOPK; k++) {
        float bv = v[0]; int bj = 0;
#pragma unroll
        for (int j = 1; j < 8; j++)
            if (v[j] > bv) { bv = v[j]; bj = j; }
        int bi = bj * 1024 + tid;

#pragma unroll
        for (int o = 16; o > 0; o >>= 1) {
            float ov = __shfl_down_sync(0xffffffffu, bv, o);
            int   oi = __shfl_down_sync(0xffffffffu, bi, o);
            if (ov > bv) { bv = ov; bi = oi; }
        }
        if ((tid & 31) == 0) { s_wv[tid >> 5] = bv; s_wi[tid >> 5] = bi; }
        __syncthreads();

        if (tid < 32) {
            bv = s_wv[tid]; bi = s_wi[tid];
#pragma unroll
            for (int o = 16; o > 0; o >>= 1) {
                float ov = __shfl_down_sync(0xffffffffu, bv, o);
                int   oi = __shfl_down_sync(0xffffffffu, bi, o);
                if (ov > bv) { bv = ov; bi = oi; }
            }
            if (tid == 0) {
                s_bi = bi;
                g_topv[d * TOPK + k] = bv;
                g_topi[d * TOPK + k] = bi;
            }
        }
        __syncthreads();

        int wi = s_bi;
        if ((wi & 1023) == tid) v[wi >> 10] = -CUDART_INF_F;
    }
}

// ---------------------------------------------------------------------------
// Kernel 2: probe. One warp handles TWO rows; each lane owns 4 features per
// row = 8 independent probe chains (MLP=8 to drive DRAM busy% up).
// smem tables are staged TRANSPOSED to [k][d] so LDS bank = d%32 = lane ->
// conflict-free under per-chain k divergence. Probe k issued only after k-1
// missed -> minimal DRAM bytes.
// ---------------------------------------------------------------------------
__global__ __launch_bounds__(512) void probe_kernel(const float* __restrict__ x,
                                                    const int*   __restrict__ adj,
                                                    float*       __restrict__ out) {
    __shared__ float s_topv[TOPK * DD];   // [k*DD + d]
    __shared__ int   s_topi[TOPK * DD];
    // Transpose on load: t enumerates [k][d]; source is [d][k].
    for (int t = threadIdx.x; t < TOPK * DD; t += blockDim.x) {
        int k = t >> 7;          // t / DD
        int d = t & (DD - 1);    // t % DD
        s_topv[t] = g_topv[d * TOPK + k];
        s_topi[t] = g_topi[d * TOPK + k];
    }
    __syncthreads();

    const int warp = threadIdx.x >> 5;
    const int lane = threadIdx.x & 31;
    const int row0 = blockIdx.x * 32 + warp * 2;   // two rows per warp

    const int* __restrict__ arow[2] = { adj + (size_t)row0 * NN,
                                        adj + (size_t)(row0 + 1) * NN };

    // chain c = r*4 + f  (r = row sel, f = feature group), d = f*32 + lane
    int      k[8]  = {0,0,0,0,0,0,0,0};
    float    res[8];
    unsigned done = 0;
    unsigned fb   = 0;

#pragma unroll 1
    while (done != 0xFFu) {
        int cc[8], a[8];
#pragma unroll
        for (int c = 0; c < 8; c++)
            if (!((done >> c) & 1))
                cc[c] = s_topi[k[c] * DD + (c & 3) * 32 + lane];
#pragma unroll
        for (int c = 0; c < 8; c++)
            if (!((done >> c) & 1))
                a[c] = __ldcs(arow[c >> 2] + cc[c]);
#pragma unroll
        for (int c = 0; c < 8; c++) {
            if (!((done >> c) & 1)) {
                if (a[c] != 0) {
                    res[c] = s_topv[k[c] * DD + (c & 3) * 32 + lane];
                    done |= 1u << c;
                } else if (++k[c] == TOPK) {
                    fb   |= 1u << c;      // exact fallback (~never: p=2^-32)
                    done |= 1u << c;
                }
            }
        }
    }

    if (fb) {  // exact fallback: full masked row scan (also no-neighbor -> 0)
#pragma unroll 1
        for (int c = 0; c < 8; c++) {
            if ((fb >> c) & 1) {
                const int d = (c & 3) * 32 + lane;
                const int* __restrict__ ar = arow[c >> 2];
                float m = -FLT_MAX; int any = 0;
                for (int j = 0; j < NN; j++) {
                    if (ar[j] != 0) { any = 1; m = fmaxf(m, x[(size_t)j * DD + d]); }
                }
                res[c] = any ? m : 0.0f;
            }
        }
    }

#pragma unroll
    for (int c = 0; c < 8; c++)
        out[(size_t)(row0 + (c >> 2)) * DD + (c & 3) * 32 + lane] = res[c];
}

extern "C" void kernel_launch(void* const* d_in, const int* in_sizes, int n_in,
                              void* d_out, int out_size) {
    const float* x   = (const float*)d_in[0];
    const int*   adj = (const int*)d_in[1];
    float*       out = (float*)d_out;

    topk_kernel<<<DD, 1024>>>(x);
    probe_kernel<<<NN / 32, 512>>>(x, adj, out);
}